// round 16
// baseline (speedup 1.0000x reference)
#include <cuda_runtime.h>
#include <cstdint>
#include <cstddef>

#define D0      128
#define NGRP    64
#define NB      256
#define TTOT    2560
#define NQUADS  4096            // 16384 tiles / 4-tile size cycle
#define GRID    152             // 1 CTA per SM
#define NTMA    10              // TMA chain warps (w0-9), layout identical to R12
#define NLDG    8               // LDG 2-pass warps (w10-17)
#define NWARPS  (NTMA + NLDG)
#define THREADS (NWARPS * 32)   // 576
#define NSPLIT  4

// ---------------- PTX helpers ----------------
__device__ __forceinline__ uint32_t smem_u32(const void* p) {
    return (uint32_t)__cvta_generic_to_shared(p);
}
__device__ __forceinline__ void mbar_init(uint32_t mbar, uint32_t cnt) {
    asm volatile("mbarrier.init.shared.b64 [%0], %1;" :: "r"(mbar), "r"(cnt) : "memory");
}
__device__ __forceinline__ void mbar_expect_tx(uint32_t mbar, uint32_t bytes) {
    asm volatile("mbarrier.arrive.expect_tx.shared.b64 _, [%0], %1;"
                 :: "r"(mbar), "r"(bytes) : "memory");
}
__device__ __forceinline__ void bulk_g2s(uint32_t dst, const void* src,
                                         uint32_t bytes, uint32_t mbar) {
    asm volatile("cp.async.bulk.shared::cluster.global.mbarrier::complete_tx::bytes "
                 "[%0], [%1], %2, [%3];"
                 :: "r"(dst), "l"(src), "r"(bytes), "r"(mbar) : "memory");
}
__device__ __forceinline__ void mbar_wait(uint32_t mbar, uint32_t parity) {
    asm volatile(
        "{\n\t.reg .pred P;\n"
        "WL%=:\n\t"
        "mbarrier.try_wait.parity.acquire.cta.shared::cta.b64 P, [%0], %1, 0x989680;\n\t"
        "@P bra WD%=;\n\t"
        "bra WL%=;\n"
        "WD%=:\n\t}"
        :: "r"(mbar), "r"(parity) : "memory");
}
__device__ __forceinline__ void fence_async() {
    asm volatile("fence.proxy.async.shared::cta;" ::: "memory");
}
__device__ __forceinline__ float4 ldcg4(const float4* p) {
    float4 v;
    asm volatile("ld.global.cg.v4.f32 {%0,%1,%2,%3}, [%4];"
                 : "=f"(v.x), "=f"(v.y), "=f"(v.z), "=f"(v.w) : "l"(p));
    return v;
}

// ---- TMA warp tables (w0-9): buffers identical to R12; strides widened ----
__device__ __constant__ int W_C[NTMA]   = { 0,0, 1,1, 2,2,2, 3,3,3 };
__device__ __constant__ int W_J[NTMA]   = { 0,1, 0,1, 0,1,2, 0,1,2 };
__device__ __constant__ int W_NW[NTMA]  = { 2,2, 3,3, 4,4,4, 5,5,5 };
__device__ __constant__ int W_OFF[NTMA] = { 0, 2048, 4096, 8192,
                                            12288, 18432, 24576,
                                            30720, 38912, 47104 };   // 55296 fl

// ---- LDG warp tables (w10-17): d = w-10 ----
// quads q = J + NW*(T + 2*i); tiles l = 4q + C
__device__ __constant__ int L_C[NLDG]  = { 1,1, 2,2, 3,3, 3,3 };
__device__ __constant__ int L_J[NLDG]  = { 2,2, 3,3, 3,3, 4,4 };
__device__ __constant__ int L_T[NLDG]  = { 0,1, 0,1, 0,1, 0,1 };
__device__ __constant__ int L_NW[NLDG] = { 3,3, 4,4, 5,5, 5,5 };

extern __shared__ float dynbuf[];   // 216 KB

__global__ __launch_bounds__(THREADS, 1)
void ragged_attn_hy2(const float* __restrict__ s_i,
                     const float* __restrict__ theta,
                     float* __restrict__ out)
{
    __shared__ __align__(8)  unsigned long long full_b[NTMA];
    __shared__ __align__(16) float scores[NWARPS][64];

    const int tid  = threadIdx.x;
    const int lane = tid & 31;
    const int w    = tid >> 5;
    const int gid  = lane >> 3;     // 8-lane token group 0..3
    const int sub  = lane & 7;      // d-quarter within token

    // quad-aligned tile range: class of tile l is l&3
    const int qs    = (int)(((long long)blockIdx.x       * NQUADS) / GRID);
    const int qe    = (int)(((long long)(blockIdx.x + 1) * NQUADS) / GRID);
    const int start = qs * 4;
    const int nq    = qe - qs;

    if (tid == 0) {
        #pragma unroll
        for (int s = 0; s < NTMA; s++) mbar_init(smem_u32(&full_b[s]), 1);
    }
    __syncthreads();   // only block barrier

    float* const srow = scores[w];

    if (w < NTMA) {
        // ================= TMA self-refilling chain (R12 protocol) =============
        const int c  = W_C[w];
        const int jw = W_J[w];
        const int nw = W_NW[w];
        const int nt = (c + 1) << 4;
        const uint32_t bytes  = (uint32_t)nt * D0 * 4u;
        const uint32_t qbytes = bytes / NSPLIT;
        const uint32_t fb  = smem_u32(&full_b[w]);
        float* const  buf  = dynbuf + W_OFF[w];
        const uint32_t dst = smem_u32(buf);
        const float4* t4   = reinterpret_cast<const float4*>(buf);

        auto src_of = [&](int q) -> const char* {
            const int id = start + 4 * q + c;
            const int g  = id & 63;
            const int t0 = (g >> 2) * 160 + c * (c + 1) * 8;
            return (const char*)(theta + ((size_t)(id >> 6) * TTOT + t0) * D0);
        };

        if (jw < nq && lane == 0) {
            mbar_expect_tx(fb, bytes);
            #pragma unroll
            for (int p = 0; p < NSPLIT; p++)
                bulk_g2s(dst + p * qbytes, src_of(jw) + p * qbytes, qbytes, fb);
        }

        for (int k = 0; ; k++) {
            const int q = jw + nw * k;
            if (q >= nq) break;

            mbar_wait(fb, (uint32_t)(k & 1));

            const int id = start + 4 * q + c;
            const int b  = id >> 6;
            const int g  = id & 63;

            const float4* const s4p =
                reinterpret_cast<const float4*>(s_i + (size_t)b * D0);
            const float4 s0 = __ldg(s4p + sub);
            const float4 s1 = __ldg(s4p + sub + 8);
            const float4 s2 = __ldg(s4p + sub + 16);
            const float4 s3 = __ldg(s4p + sub + 24);

            // phase A
            #pragma unroll 4
            for (int tk = gid; tk < nt; tk += 4) {
                const float4 v0 = t4[tk * 32 + sub];
                const float4 v1 = t4[tk * 32 + sub + 8];
                const float4 v2 = t4[tk * 32 + sub + 16];
                const float4 v3 = t4[tk * 32 + sub + 24];
                float x = v0.x*s0.x + v0.y*s0.y + v0.z*s0.z + v0.w*s0.w
                        + v1.x*s1.x + v1.y*s1.y + v1.z*s1.z + v1.w*s1.w
                        + v2.x*s2.x + v2.y*s2.y + v2.z*s2.z + v2.w*s2.w
                        + v3.x*s3.x + v3.y*s3.y + v3.z*s3.z + v3.w*s3.w;
                x += __shfl_xor_sync(0xffffffffu, x, 4);
                x += __shfl_xor_sync(0xffffffffu, x, 2);
                x += __shfl_xor_sync(0xffffffffu, x, 1);
                if (sub == 0) srow[tk] = x * (1.0f / 128.0f);   // / d0
            }
            __syncwarp();

            // phase B
            const float a0 = (lane      < nt) ? srow[lane]      : -3.4e38f;
            const float a1 = (lane + 32 < nt) ? srow[lane + 32] : -3.4e38f;
            float mx = fmaxf(a0, a1);
            #pragma unroll
            for (int o = 16; o > 0; o >>= 1)
                mx = fmaxf(mx, __shfl_xor_sync(0xffffffffu, mx, o));
            const float e0 = (lane      < nt) ? __expf(a0 - mx) : 0.0f;
            const float e1 = (lane + 32 < nt) ? __expf(a1 - mx) : 0.0f;
            float sd = e0 + e1;
            #pragma unroll
            for (int o = 16; o > 0; o >>= 1)
                sd += __shfl_xor_sync(0xffffffffu, sd, o);
            const float inv = 1.0f / sd;
            const float wl = e0 * inv;
            const float wh = e1 * inv;

            // phase C
            float4 acc = make_float4(0.f, 0.f, 0.f, 0.f);
            for (int t = 0; t < nt; t += 4) {
                const float base = (t < 32) ? wl : wh;
                const float w0 = __shfl_sync(0xffffffffu, base, (t + 0) & 31);
                const float w1 = __shfl_sync(0xffffffffu, base, (t + 1) & 31);
                const float w2 = __shfl_sync(0xffffffffu, base, (t + 2) & 31);
                const float w3 = __shfl_sync(0xffffffffu, base, (t + 3) & 31);
                const float4 va = t4[(t + 0) * 32 + lane];
                const float4 vb = t4[(t + 1) * 32 + lane];
                const float4 vc = t4[(t + 2) * 32 + lane];
                const float4 vd = t4[(t + 3) * 32 + lane];
                acc.x += w0*va.x + w1*vb.x + w2*vc.x + w3*vd.x;
                acc.y += w0*va.y + w1*vb.y + w2*vc.y + w3*vd.y;
                acc.z += w0*va.z + w1*vb.z + w2*vc.z + w3*vd.z;
                acc.w += w0*va.w + w1*vb.w + w2*vc.w + w3*vd.w;
            }
            reinterpret_cast<float4*>(out + ((size_t)b * NGRP + g) * D0)[lane] = acc;

            __syncwarp();   // buffer reads complete

            const int qn = jw + nw * (k + 1);
            if (qn < nq && lane == 0) {
                fence_async();
                mbar_expect_tx(fb, bytes);
                #pragma unroll
                for (int p = 0; p < NSPLIT; p++)
                    bulk_g2s(dst + p * qbytes, src_of(qn) + p * qbytes, qbytes, fb);
            }
        }
    } else {
        // ================= LDG 2-pass chain (L1tex path) =======================
        const int d  = w - NTMA;
        const int c  = L_C[d];
        const int jp = L_J[d];
        const int tm = L_T[d];
        const int nw = L_NW[d];
        const int nt = (c + 1) << 4;

        for (int i = 0; ; i++) {
            const int q = jp + nw * (tm + 2 * i);
            if (q >= nq) break;

            const int id = start + 4 * q + c;
            const int b  = id >> 6;
            const int g  = id & 63;
            const int t0 = (g >> 2) * 160 + c * (c + 1) * 8;
            const float4* g4 = reinterpret_cast<const float4*>(
                theta + ((size_t)b * TTOT + t0) * D0);

            const float4* const s4p =
                reinterpret_cast<const float4*>(s_i + (size_t)b * D0);
            const float4 s0 = __ldg(s4p + sub);
            const float4 s1 = __ldg(s4p + sub + 8);
            const float4 s2 = __ldg(s4p + sub + 16);
            const float4 s3 = __ldg(s4p + sub + 24);

            // pass 1: DRAM stream via L2, fused dot
            #pragma unroll 4
            for (int tk = gid; tk < nt; tk += 4) {
                const float4 v0 = ldcg4(g4 + tk * 32 + sub);
                const float4 v1 = ldcg4(g4 + tk * 32 + sub + 8);
                const float4 v2 = ldcg4(g4 + tk * 32 + sub + 16);
                const float4 v3 = ldcg4(g4 + tk * 32 + sub + 24);
                float x = v0.x*s0.x + v0.y*s0.y + v0.z*s0.z + v0.w*s0.w
                        + v1.x*s1.x + v1.y*s1.y + v1.z*s1.z + v1.w*s1.w
                        + v2.x*s2.x + v2.y*s2.y + v2.z*s2.z + v2.w*s2.w
                        + v3.x*s3.x + v3.y*s3.y + v3.z*s3.z + v3.w*s3.w;
                x += __shfl_xor_sync(0xffffffffu, x, 4);
                x += __shfl_xor_sync(0xffffffffu, x, 2);
                x += __shfl_xor_sync(0xffffffffu, x, 1);
                if (sub == 0) srow[tk] = x * (1.0f / 128.0f);
            }
            __syncwarp();

            // softmax (generic nt up to 64)
            const float a0 = (lane      < nt) ? srow[lane]      : -3.4e38f;
            const float a1 = (lane + 32 < nt) ? srow[lane + 32] : -3.4e38f;
            float mx = fmaxf(a0, a1);
            #pragma unroll
            for (int o = 16; o > 0; o >>= 1)
                mx = fmaxf(mx, __shfl_xor_sync(0xffffffffu, mx, o));
            const float e0 = (lane      < nt) ? __expf(a0 - mx) : 0.0f;
            const float e1 = (lane + 32 < nt) ? __expf(a1 - mx) : 0.0f;
            float sd = e0 + e1;
            #pragma unroll
            for (int o = 16; o > 0; o >>= 1)
                sd += __shfl_xor_sync(0xffffffffu, sd, o);
            const float inv = 1.0f / sd;
            const float wl = e0 * inv;
            const float wh = e1 * inv;

            // pass 2: L2 re-read (tile just fetched), weighted sum
            float4 acc = make_float4(0.f, 0.f, 0.f, 0.f);
            for (int t = 0; t < nt; t += 4) {
                const float base = (t < 32) ? wl : wh;
                const float w0 = __shfl_sync(0xffffffffu, base, (t + 0) & 31);
                const float w1 = __shfl_sync(0xffffffffu, base, (t + 1) & 31);
                const float w2 = __shfl_sync(0xffffffffu, base, (t + 2) & 31);
                const float w3 = __shfl_sync(0xffffffffu, base, (t + 3) & 31);
                const float4 va = ldcg4(g4 + (t + 0) * 32 + lane);
                const float4 vb = ldcg4(g4 + (t + 1) * 32 + lane);
                const float4 vc = ldcg4(g4 + (t + 2) * 32 + lane);
                const float4 vd = ldcg4(g4 + (t + 3) * 32 + lane);
                acc.x += w0*va.x + w1*vb.x + w2*vc.x + w3*vd.x;
                acc.y += w0*va.y + w1*vb.y + w2*vc.y + w3*vd.y;
                acc.z += w0*va.z + w1*vb.z + w2*vc.z + w3*vd.z;
                acc.w += w0*va.w + w1*vb.w + w2*vc.w + w3*vd.w;
            }
            reinterpret_cast<float4*>(out + ((size_t)b * NGRP + g) * D0)[lane] = acc;
        }
    }
}

extern "C" void kernel_launch(void* const* d_in, const int* in_sizes, int n_in,
                              void* d_out, int out_size)
{
    const float* s_i   = (const float*)d_in[0];   // [256,128]
    const float* theta = (const float*)d_in[1];   // [256,2560,128]
    float* out = (float*)d_out;                   // [256,64,128]
    (void)in_sizes; (void)n_in; (void)out_size;

    const size_t dyn = 55296 * sizeof(float);     // 216 KB (R12 layout)
    cudaFuncSetAttribute(ragged_attn_hy2,
                         cudaFuncAttributeMaxDynamicSharedMemorySize, (int)dyn);
    ragged_attn_hy2<<<GRID, THREADS, dyn>>>(s_i, theta, out);
}

// round 17
// speedup vs baseline: 1.1648x; 1.1648x over previous
#include <cuda_runtime.h>
#include <cstdint>
#include <cstddef>

#define D0      128
#define NGRP    64
#define NB      256
#define TTOT    2560
#define NQUADS  4096            // 16384 tiles / 4-tile size cycle
#define GRID    152             // 1 CTA per SM
#define NWARPS  10              // class-pinned self-refilling chains (R12 layout)
#define THREADS (NWARPS * 32)

// ---------------- PTX helpers ----------------
__device__ __forceinline__ uint32_t smem_u32(const void* p) {
    return (uint32_t)__cvta_generic_to_shared(p);
}
__device__ __forceinline__ void cp16(uint32_t smem, const void* gmem) {
    asm volatile("cp.async.cg.shared.global [%0], [%1], 16;"
                 :: "r"(smem), "l"(gmem) : "memory");
}
__device__ __forceinline__ void cp_commit() {
    asm volatile("cp.async.commit_group;" ::: "memory");
}
__device__ __forceinline__ void cp_wait_all() {
    asm volatile("cp.async.wait_group 0;" ::: "memory");
}

// warp -> (class, index-in-class, warps-in-class, buffer float offset)
// classes sized 16/32/48/64 tokens = 8/16/24/32 KB; warps per class {2,2,3,3}
__device__ __constant__ int W_C[NWARPS]   = { 0,0, 1,1, 2,2,2, 3,3,3 };
__device__ __constant__ int W_J[NWARPS]   = { 0,1, 0,1, 0,1,2, 0,1,2 };
__device__ __constant__ int W_NW[NWARPS]  = { 2,2, 2,2, 3,3,3, 3,3,3 };
__device__ __constant__ int W_OFF[NWARPS] = { 0, 2048, 4096, 8192,
                                              12288, 18432, 24576,
                                              30720, 38912, 47104 };   // 55296 fl

extern __shared__ float dynbuf[];   // 216 KB

__global__ __launch_bounds__(THREADS, 1)
void ragged_attn_cp(const float* __restrict__ s_i,
                    const float* __restrict__ theta,
                    float* __restrict__ out)
{
    __shared__ __align__(16) float scores[NWARPS][64];

    const int tid  = threadIdx.x;
    const int lane = tid & 31;
    const int w    = tid >> 5;
    const int gid  = lane >> 3;     // 8-lane token group 0..3
    const int sub  = lane & 7;      // d-quarter within token

    // quad-aligned tile range: class of tile l is l&3
    const int qs    = (int)(((long long)blockIdx.x       * NQUADS) / GRID);
    const int qe    = (int)(((long long)(blockIdx.x + 1) * NQUADS) / GRID);
    const int start = qs * 4;
    const int n     = (qe - qs) * 4;

    const int c  = W_C[w];
    const int jw = W_J[w];
    const int nw = W_NW[w];
    const int nt = (c + 1) << 4;                 // loop-invariant tokens
    float* const  buf  = dynbuf + W_OFF[w];
    const uint32_t dst = smem_u32(buf) + (uint32_t)lane * 16u;
    const float4* t4   = reinterpret_cast<const float4*>(buf);
    float* const  srow = scores[w];

    // source address of tile l (class c fixed); per-lane 16B slice base
    auto src_of = [&](int l) -> const char* {
        const int id = start + l;
        const int g  = id & 63;
        const int t0 = (g >> 2) * 160 + c * (c + 1) * 8;
        return (const char*)(theta + ((size_t)(id >> 6) * TTOT + t0) * D0)
               + (size_t)lane * 16u;
    };

    // fill = nt per-lane 16B copies, stride 512B (tile bytes = nt*512)
    auto fill = [&](const char* src) {
        #pragma unroll 8
        for (int i = 0; i < nt; i++)
            cp16(dst + (uint32_t)i * 512u, src + (size_t)i * 512u);
        cp_commit();
    };

    // prologue: first tile
    {
        const int l0 = 4 * jw + c;
        if (l0 < n) fill(src_of(l0));
    }

    for (int k = 0; ; k++) {
        const int l = 4 * (jw + nw * k) + c;
        if (l >= n) break;

        cp_wait_all();        // own lane's copies complete
        __syncwarp();         // all lanes' copies complete -> tile visible

        const int id = start + l;
        const int b  = id >> 6;
        const int g  = id & 63;

        const float4* const s4p =
            reinterpret_cast<const float4*>(s_i + (size_t)b * D0);
        const float4 s0 = __ldg(s4p + sub);
        const float4 s1 = __ldg(s4p + sub + 8);
        const float4 s2 = __ldg(s4p + sub + 16);
        const float4 s3 = __ldg(s4p + sub + 24);

        // ---- phase A: scores; 4 tokens per pass, 8 lanes per token ----
        #pragma unroll 4
        for (int tk = gid; tk < nt; tk += 4) {
            const float4 v0 = t4[tk * 32 + sub];
            const float4 v1 = t4[tk * 32 + sub + 8];
            const float4 v2 = t4[tk * 32 + sub + 16];
            const float4 v3 = t4[tk * 32 + sub + 24];
            float x = v0.x*s0.x + v0.y*s0.y + v0.z*s0.z + v0.w*s0.w
                    + v1.x*s1.x + v1.y*s1.y + v1.z*s1.z + v1.w*s1.w
                    + v2.x*s2.x + v2.y*s2.y + v2.z*s2.z + v2.w*s2.w
                    + v3.x*s3.x + v3.y*s3.y + v3.z*s3.z + v3.w*s3.w;
            x += __shfl_xor_sync(0xffffffffu, x, 4);
            x += __shfl_xor_sync(0xffffffffu, x, 2);
            x += __shfl_xor_sync(0xffffffffu, x, 1);
            if (sub == 0) srow[tk] = x * (1.0f / 128.0f);   // / d0
        }
        __syncwarp();

        // ---- phase B: in-warp softmax; weights kept in registers ----
        const float a0 = (lane      < nt) ? srow[lane]      : -3.4e38f;
        const float a1 = (lane + 32 < nt) ? srow[lane + 32] : -3.4e38f;
        float mx = fmaxf(a0, a1);
        #pragma unroll
        for (int o = 16; o > 0; o >>= 1)
            mx = fmaxf(mx, __shfl_xor_sync(0xffffffffu, mx, o));
        const float e0 = (lane      < nt) ? __expf(a0 - mx) : 0.0f;
        const float e1 = (lane + 32 < nt) ? __expf(a1 - mx) : 0.0f;
        float sd = e0 + e1;
        #pragma unroll
        for (int o = 16; o > 0; o >>= 1)
            sd += __shfl_xor_sync(0xffffffffu, sd, o);
        const float inv = 1.0f / sd;
        const float wl = e0 * inv;
        const float wh = e1 * inv;

        // ---- phase C: weighted sum; weights broadcast via shuffle ----
        float4 acc = make_float4(0.f, 0.f, 0.f, 0.f);
        for (int t = 0; t < nt; t += 4) {
            const float base = (t < 32) ? wl : wh;
            const float w0 = __shfl_sync(0xffffffffu, base, (t + 0) & 31);
            const float w1 = __shfl_sync(0xffffffffu, base, (t + 1) & 31);
            const float w2 = __shfl_sync(0xffffffffu, base, (t + 2) & 31);
            const float w3 = __shfl_sync(0xffffffffu, base, (t + 3) & 31);
            const float4 va = t4[(t + 0) * 32 + lane];
            const float4 vb = t4[(t + 1) * 32 + lane];
            const float4 vc = t4[(t + 2) * 32 + lane];
            const float4 vd = t4[(t + 3) * 32 + lane];
            acc.x += w0*va.x + w1*vb.x + w2*vc.x + w3*vd.x;
            acc.y += w0*va.y + w1*vb.y + w2*vc.y + w3*vd.y;
            acc.z += w0*va.z + w1*vb.z + w2*vc.z + w3*vd.z;
            acc.w += w0*va.w + w1*vb.w + w2*vc.w + w3*vd.w;
        }
        reinterpret_cast<float4*>(out + ((size_t)b * NGRP + g) * D0)[lane] = acc;

        __syncwarp();   // all lanes done reading buf -> safe to overwrite

        // ---- self-refill next tile ----
        const int ln = 4 * (jw + nw * (k + 1)) + c;
        if (ln < n) fill(src_of(ln));
    }
}

extern "C" void kernel_launch(void* const* d_in, const int* in_sizes, int n_in,
                              void* d_out, int out_size)
{
    const float* s_i   = (const float*)d_in[0];   // [256,128]
    const float* theta = (const float*)d_in[1];   // [256,2560,128]
    float* out = (float*)d_out;                   // [256,64,128]
    (void)in_sizes; (void)n_in; (void)out_size;

    const size_t dyn = 55296 * sizeof(float);     // 216 KB (R12 layout)
    cudaFuncSetAttribute(ragged_attn_cp,
                         cudaFuncAttributeMaxDynamicSharedMemorySize, (int)dyn);
    ragged_attn_cp<<<GRID, THREADS, dyn>>>(s_i, theta, out);
}